// round 9
// baseline (speedup 1.0000x reference)
#include <cuda_runtime.h>
#include <math.h>

#define DD 512
#define PP 36
#define PS 37                     // 36 data + mean in pad; odd stride -> conflict-free
#define NT 1024
#define NC 512                    // consumer threads (warps 0-15)
#define EPSN 1e-12f
#define SCALE_CLS 7.0f
#define TILE_F (DD*PP)            // 18432 floats per gmem tile
#define SLOT_F (DD*PS)            // 18944 floats per smem slot

// SMEM float offsets after the 3 ring slots
#define NTARR (3*SLOT_F)          // test per-position norms (persist 1 iter) [40]
#define NRARR (NTARR+40)          // train norms [40]
#define SCTE  (NRARR+40)          // test selection scores [40]
#define SCTR  (SCTE+40)           // train selection scores [40]
#define WWA   (SCTR+40)           // fuse weights [72] (pad 80)
#define REDA  (WWA+80)            // stage-A reduction scratch [48]
#define REDD  (REDA+48)           // final reduction scratch [48]
#define SMEMF (REDD+48)
#define SMEMB (SMEMF*4)           // 228,672 B (<= 232,448 max dynamic)

__device__ __forceinline__ float warp_sum(float v) {
#pragma unroll
    for (int o = 16; o > 0; o >>= 1) v += __shfl_down_sync(0xffffffffu, v, o);
    return v;
}

#define CBAR() asm volatile("bar.sync 1, 512;" ::: "memory")

// producer: load one tile (R1's proven coalesced pattern) into a slot
__device__ __forceinline__ void prod_load(const float* __restrict__ src,
                                          float* __restrict__ dst, int pt) {
    float4 v[9];
    const float4* s4 = (const float4*)src;
#pragma unroll
    for (int k = 0; k < 9; k++) v[k] = s4[pt + k * NC];
#pragma unroll
    for (int k = 0; k < 9; k++) {
        int j  = pt + k * NC;
        int dd = j / 9;
        int p  = (j - dd * 9) * 4;
        float* r = dst + dd * PS + p;
        r[0] = v[k].x; r[1] = v[k].y; r[2] = v[k].z; r[3] = v[k].w;
    }
}

__global__ __launch_bounds__(NT, 1)
void fused_region_score_ws(const float* __restrict__ ftrain,
                           const float* __restrict__ ftest,
                           const int*   __restrict__ Kp,
                           float* __restrict__ out,
                           int groups, int halfOut)
{
    extern __shared__ float sm[];
    float* redA = sm + REDA;
    float* redD = sm + REDD;

    const int tid  = threadIdx.x;
    const bool prod = (tid >= NC);
    const int pt   = tid - NC;           // producer thread id
    const int lane = tid & 31;
    const int cw   = tid >> 5;           // consumer warp 0..15
    const int K    = Kp[0];

    // contiguous group range per CTA
    const int ncta = gridDim.x;
    const int q  = groups / ncta, r = groups % ncta;
    const int gbeg = blockIdx.x * q + min(blockIdx.x, r);
    const int gend = gbeg + q + (blockIdx.x < r ? 1 : 0);
    if (gbeg >= gend) return;

    int iT = 0, iR = 1, iF = 2;          // slot indices: test, train, free

    // ================= prologue =================
    if (prod) prod_load(ftest + (size_t)gbeg * TILE_F, sm + 0 * SLOT_F, pt);
    __syncthreads();
    if (!prod) {
        // mean-test(gbeg) -> pad column
        float* T = sm;
        const float* row = T + tid * PS;
        float s = 0.f;
#pragma unroll
        for (int p = 0; p < PP; p++) s += row[p];
        T[tid * PS + PP] = s * (1.0f / PP);
        // n_t(gbeg): 36 norm jobs over 16 warps
#pragma unroll
        for (int rr = 0; rr < 3; rr++) {
            if (rr == 2 && cw >= 4) break;
            const int p = cw + 16 * rr;
            float a2 = 0.f;
#pragma unroll
            for (int i = 0; i < DD / 32; i++) {
                float a = T[(lane + 32 * i) * PS + p];
                a2 += a * a;
            }
            a2 = warp_sum(a2);
            if (lane == 0) sm[NTARR + p] = fmaxf(sqrtf(a2), EPSN);
        }
    } else {
        prod_load(ftrain + (size_t)gbeg * TILE_F, sm + 1 * SLOT_F, pt);
    }
    __syncthreads();

    // ================= main loop =================
    for (int g = gbeg; g < gend; g++) {
        float* T = sm + iT * SLOT_F;     // test(g)  [means in pad]
        float* R = sm + iR * SLOT_F;     // train(g)
        float* F = sm + iF * SLOT_F;     // free -> test(g+1)
        const bool more = (g + 1 < gend);

        float u = 0.f, v = 0.f;

        if (!prod) {
            // ---- mean-train: thread d sums its row -> pad ------------------
            {
                const float* row = R + tid * PS;
                float s = 0.f;
#pragma unroll
                for (int p = 0; p < PP; p++) s += row[p];
                R[tid * PS + PP] = s * (1.0f / PP);
            }
            CBAR();                       // means visible to all consumers

            // ---- stage A partials -----------------------------------------
            {
                float mt = T[tid * PS + PP];
                float mr = R[tid * PS + PP];
                float a = warp_sum(mt * mr);
                float b = warp_sum(mt * mt);
                float c = warp_sum(mr * mr);
                if (lane == 0) { redA[cw] = a; redA[16 + cw] = b; redA[32 + cw] = c; }
            }

            // ---- stage B: 72 jobs over 16 warps -----------------------------
#pragma unroll
            for (int rr = 0; rr < 5; rr++) {
                if (rr == 4 && cw >= 8) break;
                const int j = cw + 16 * rr;       // 0..71
                if (j < PP) {
                    // ta_test[p] = sum_d x_test * m_train ; sc_te = ta/n_t
                    const int p = j;
                    float ta = 0.f;
#pragma unroll
                    for (int i = 0; i < DD / 32; i++) {
                        int dd = lane + 32 * i;
                        ta += T[dd * PS + p] * R[dd * PS + PP];
                    }
                    ta = warp_sum(ta);
                    if (lane == 0) sm[SCTE + p] = ta / sm[NTARR + p];
                } else {
                    // train: norm + ta vs m_test
                    const int p = j - PP;
                    float a2 = 0.f, ta = 0.f;
#pragma unroll
                    for (int i = 0; i < DD / 32; i++) {
                        int dd = lane + 32 * i;
                        float a = R[dd * PS + p];
                        a2 += a * a;
                        ta += a * T[dd * PS + PP];
                    }
                    a2 = warp_sum(a2);
                    ta = warp_sum(ta);
                    if (lane == 0) {
                        float n = fmaxf(sqrtf(a2), EPSN);
                        sm[NRARR + p] = n;
                        sm[SCTR + p]  = ta / n;
                    }
                }
            }
            CBAR();                       // sc/nr + redA visible

            // ---- stage A final ----------------------------------------------
            if (cw == 0) {
                float a = (lane < 16) ? redA[lane]      : 0.f;
                float b = (lane < 16) ? redA[16 + lane] : 0.f;
                float c = (lane < 16) ? redA[32 + lane] : 0.f;
                a = warp_sum(a); b = warp_sum(b); c = warp_sum(c);
                if (lane == 0) {
                    float den = fmaxf(sqrtf(b), EPSN) * fmaxf(sqrtf(c), EPSN);
                    out[g] = SCALE_CLS * a / den;
                }
            }

            // ---- stage C: top-K via rank counting ---------------------------
            if (tid < 2 * PP) {
                const int tens = (tid >= PP) ? 1 : 0;
                const int p    = tid - PP * tens;
                const int sco  = tens ? SCTR : SCTE;
                const float sv = sm[sco + p];
                int rank = 0;
#pragma unroll
                for (int qq = 0; qq < PP; qq++) {
                    float o = sm[sco + qq];
                    rank += (o > sv) || (o == sv && qq < p);  // lower index wins
                }
                float n = tens ? sm[NRARR + p] : sm[NTARR + p];
                sm[WWA + tid] = (rank < K) ? (1.0f / n) : 0.0f;
            }
            CBAR();                       // weights visible

            // ---- stage D: fused vectors, weights via shfl -------------------
            {
                float wt_lo = sm[WWA + lane];
                float wt_hi = (lane < 4) ? sm[WWA + 32 + lane] : 0.f;
                float wr_lo = sm[WWA + 36 + lane];
                float wr_hi = (lane < 4) ? sm[WWA + 68 + lane] : 0.f;
                const float* rT = T + tid * PS;
                const float* rR = R + tid * PS;
#pragma unroll
                for (int p = 0; p < 32; p++) {
                    u += rT[p] * __shfl_sync(0xffffffffu, wt_lo, p);
                    v += rR[p] * __shfl_sync(0xffffffffu, wr_lo, p);
                }
#pragma unroll
                for (int p = 0; p < 4; p++) {
                    u += rT[32 + p] * __shfl_sync(0xffffffffu, wt_hi, p);
                    v += rR[32 + p] * __shfl_sync(0xffffffffu, wr_hi, p);
                }
            }
        } else if (more) {
            // producer: test(g+1) -> free slot (overlaps all compute above)
            prod_load(ftest + (size_t)(g + 1) * TILE_F, F, pt);
        }

        __syncthreads();                  // S1: F ready; T,R reads complete

        if (!prod) {
            // ---- final score partials ---------------------------------------
            {
                float a = warp_sum(u * v);
                float b = warp_sum(u * u);
                float c = warp_sum(v * v);
                if (lane == 0) { redD[cw] = a; redD[16 + cw] = b; redD[32 + cw] = c; }
            }
            CBAR();
            if (cw == 0) {
                float a = (lane < 16) ? redD[lane]      : 0.f;
                float b = (lane < 16) ? redD[16 + lane] : 0.f;
                float c = (lane < 16) ? redD[32 + lane] : 0.f;
                a = warp_sum(a); b = warp_sum(b); c = warp_sum(c);
                if (lane == 0) {
                    float den = fmaxf(sqrtf(b), EPSN) * fmaxf(sqrtf(c), EPSN);
                    out[halfOut + g] = SCALE_CLS * a / den;
                }
            }
            // ---- early work on test(g+1): mean + norms (overlaps train load)
            if (more) {
                const float* row = F + tid * PS;
                float s = 0.f;
#pragma unroll
                for (int p = 0; p < PP; p++) s += row[p];
                F[tid * PS + PP] = s * (1.0f / PP);
#pragma unroll
                for (int rr = 0; rr < 3; rr++) {
                    if (rr == 2 && cw >= 4) break;
                    const int p = cw + 16 * rr;
                    float a2 = 0.f;
#pragma unroll
                    for (int i = 0; i < DD / 32; i++) {
                        float a = F[(lane + 32 * i) * PS + p];
                        a2 += a * a;
                    }
                    a2 = warp_sum(a2);
                    if (lane == 0) sm[NTARR + p] = fmaxf(sqrtf(a2), EPSN);
                }
            }
        } else if (more) {
            // producer: train(g+1) -> old test slot (just freed)
            prod_load(ftrain + (size_t)(g + 1) * TILE_F, T, pt);
        }

        __syncthreads();                  // S2: train(g+1) + ntArr + pads ready

        // rotate slots: (T,R,F) <- (F,T,R)
        int t = iT; iT = iF; iF = iR; iR = t;
    }
}

extern "C" void kernel_launch(void* const* d_in, const int* in_sizes, int n_in,
                              void* d_out, int out_size)
{
    const float* ftrain = (const float*)d_in[0];
    const float* ftest  = (const float*)d_in[1];
    const int*   Kp     = (const int*)d_in[2];
    float* out = (float*)d_out;

    const int groups  = in_sizes[0] / (DD * PP);   // 1500
    const int halfOut = out_size / 2;              // 1500

    cudaFuncSetAttribute(fused_region_score_ws,
                         cudaFuncAttributeMaxDynamicSharedMemorySize, SMEMB);
    fused_region_score_ws<<<148, NT, SMEMB>>>(ftrain, ftest, Kp, out,
                                              groups, halfOut);
}

// round 11
// speedup vs baseline: 1.3571x; 1.3571x over previous
#include <cuda_runtime.h>
#include <math.h>

#define DD 512
#define PP 36
#define PS 37          // padded SMEM row stride: conflict-free row & column access
#define NTHREADS 512
#define EPSN 1e-12f
#define SCALE_CLS 7.0f
#define TILE_F (DD*PP)               // 18432 floats per tile
#define NJ (TILE_F/4)                // 4608 float4 jobs per tile

// SMEM layout (floats)
#define ST_OFF     0                 // test tile  [512][37]
#define SR_OFF     (DD*PS)           // train tile [512][37]
#define PT_OFF     (2*DD*PS)         // partial sums test  [4608]
#define PR_OFF     (PT_OFF + NJ)     // partial sums train [4608]
#define MT_OFF     (PR_OFF + NJ)     // mean test  [512]
#define MR_OFF     (MT_OFF + DD)     // mean train [512]
#define NT_OFF     (MR_OFF + DD)     // norms test [40]
#define NR_OFF     (NT_OFF + 40)
#define STE_OFF    (NR_OFF + 40)     // sel scores test [40]
#define STR_OFF    (STE_OFF + 40)
#define WT_OFF     (STR_OFF + 40)    // fuse weights [40]
#define WR_OFF     (WT_OFF + 40)
#define RED_OFF    (WR_OFF + 40)     // reduction scratch [48]
#define SMEM_FLOATS (RED_OFF + 48)
#define SMEM_BYTES  (SMEM_FLOATS * 4)   // ~194 KB (< 227 KB)

__device__ __forceinline__ float warp_sum(float v) {
#pragma unroll
    for (int o = 16; o > 0; o >>= 1) v += __shfl_down_sync(0xffffffffu, v, o);
    return v;
}

__global__ __launch_bounds__(NTHREADS, 1)
void fused_region_score_v2(const float* __restrict__ ftrain,
                           const float* __restrict__ ftest,
                           const int*   __restrict__ Kp,
                           float* __restrict__ out,
                           int halfOut)
{
    extern __shared__ float sm[];
    float* st     = sm + ST_OFF;
    float* sr     = sm + SR_OFF;
    float* pt     = sm + PT_OFF;
    float* pr     = sm + PR_OFF;
    float* mean_t = sm + MT_OFF;
    float* mean_r = sm + MR_OFF;
    float* nt     = sm + NT_OFF;
    float* nr     = sm + NR_OFF;
    float* s_te   = sm + STE_OFF;
    float* s_tr   = sm + STR_OFF;
    float* wt     = sm + WT_OFF;
    float* wr     = sm + WR_OFF;
    float* red    = sm + RED_OFF;

    const int g    = blockIdx.x;
    const int tid  = threadIdx.x;
    const int lane = tid & 31;
    const int wid  = tid >> 5;
    const int K    = Kp[0];

    // ---------------- load tiles (R1 coalesced) + per-float4 partial sums ---
    {
        const float4* gt = (const float4*)(ftest  + (size_t)g * TILE_F);
        const float4* gr = (const float4*)(ftrain + (size_t)g * TILE_F);
#pragma unroll
        for (int k = 0; k < 9; k++) {
            int j = tid + k * NTHREADS;       // 0..4607, coalesced
            float4 a = gt[j];
            float4 b = gr[j];
            int d = j / 9;
            int p = (j - d * 9) * 4;
            int s = d * PS + p;
            st[s] = a.x; st[s+1] = a.y; st[s+2] = a.z; st[s+3] = a.w;
            sr[s] = b.x; sr[s+1] = b.y; sr[s+2] = b.z; sr[s+3] = b.w;
            pt[j] = a.x + a.y + a.z + a.w;    // partial row sums (fused means)
            pr[j] = b.x + b.y + b.z + b.w;
        }
    }
    __syncthreads();                          // s1: tiles + partials ready

    // ---------------- mean pass: 9 scalar reads per tensor (stride 9, CF) ---
    {
        const int d = tid;
        float sa = 0.f, sb = 0.f;
#pragma unroll
        for (int k = 0; k < 9; k++) { sa += pt[9*d + k]; sb += pr[9*d + k]; }
        float mt = sa * (1.0f / PP);
        float mr = sb * (1.0f / PP);
        mean_t[d] = mt;
        mean_r[d] = mr;
        // stage A partials while values are live
        float mm  = warp_sum(mt * mr);
        float mt2 = warp_sum(mt * mt);
        float mr2 = warp_sum(mr * mr);
        if (lane == 0) { red[wid] = mm; red[16 + wid] = mt2; red[32 + wid] = mr2; }
    }
    __syncthreads();                          // s2: means + redA ready

    // ---------------- stage B: register-cached means, 1 LDS per array -------
    {
        // cache the 16 mean values this lane ever touches (32 regs)
        float mtc[16], mrc[16];
#pragma unroll
        for (int i = 0; i < 16; i++) {
            mtc[i] = mean_t[lane + 32 * i];
            mrc[i] = mean_r[lane + 32 * i];
        }
#pragma unroll
        for (int rr = 0; rr < 3; rr++) {
            if (rr == 2 && wid >= 4) break;
            const int p = wid + 16 * rr;      // 0..35
            float a2 = 0.f, b2 = 0.f, ta = 0.f, tb = 0.f;
#pragma unroll
            for (int i = 0; i < 16; i++) {
                int d = lane + 32 * i;
                float a = st[d * PS + p];
                float b = sr[d * PS + p];
                a2 += a * a;
                b2 += b * b;
                ta += a * mrc[i];             // test vs mean_train
                tb += b * mtc[i];             // train vs mean_test
            }
            a2 = warp_sum(a2); b2 = warp_sum(b2);
            ta = warp_sum(ta); tb = warp_sum(tb);
            if (lane == 0) {
                float na = fmaxf(sqrtf(a2), EPSN);
                float nb = fmaxf(sqrtf(b2), EPSN);
                nt[p] = na;  s_te[p] = ta / na;   // positive factors cancel in ranking
                nr[p] = nb;  s_tr[p] = tb / nb;
            }
        }
    }
    __syncthreads();                          // s3: scores/norms ready

    // ---------------- stage A final + stage C (same barrier section) --------
    if (wid == 0) {
        float a = (lane < 16) ? red[lane]      : 0.f;
        float b = (lane < 16) ? red[16 + lane] : 0.f;
        float c = (lane < 16) ? red[32 + lane] : 0.f;
        a = warp_sum(a); b = warp_sum(b); c = warp_sum(c);
        if (lane == 0) {
            float den = fmaxf(sqrtf(b), EPSN) * fmaxf(sqrtf(c), EPSN);
            out[g] = SCALE_CLS * a / den;
        }
    }
    if (tid >= 64 && tid < 64 + PP) {         // warp 2-3: test top-K
        const int p = tid - 64;
        const float sv = s_te[p];
        int rank = 0;
#pragma unroll
        for (int q = 0; q < PP; q++) {
            float o = s_te[q];
            rank += (o > sv) || (o == sv && q < p);   // lower index wins ties
        }
        wt[p] = (rank < K) ? (1.0f / nt[p]) : 0.0f;
    }
    if (tid >= 128 && tid < 128 + PP) {       // warp 4-5: train top-K
        const int p = tid - 128;
        const float sv = s_tr[p];
        int rank = 0;
#pragma unroll
        for (int q = 0; q < PP; q++) {
            float o = s_tr[q];
            rank += (o > sv) || (o == sv && q < p);
        }
        wr[p] = (rank < K) ? (1.0f / nr[p]) : 0.0f;
    }
    __syncthreads();                          // s4: weights ready

    // ---------------- stage D: fused features + final score -----------------
    {
        const int d = tid;
        const float* rt = st + d * PS;
        const float* rr = sr + d * PS;
        float u = 0.f, v = 0.f;
#pragma unroll
        for (int p = 0; p < PP; p++) {
            u += rt[p] * wt[p];               // weight reads are broadcasts (1 wf)
            v += rr[p] * wr[p];
        }
        float uv = warp_sum(u * v);
        float uu = warp_sum(u * u);
        float vv = warp_sum(v * v);
        if (lane == 0) { red[wid] = uv; red[16 + wid] = uu; red[32 + wid] = vv; }
    }
    __syncthreads();                          // s5: redD ready

    if (wid == 0) {
        float a = (lane < 16) ? red[lane]      : 0.f;
        float b = (lane < 16) ? red[16 + lane] : 0.f;
        float c = (lane < 16) ? red[32 + lane] : 0.f;
        a = warp_sum(a); b = warp_sum(b); c = warp_sum(c);
        if (lane == 0) {
            float den = fmaxf(sqrtf(b), EPSN) * fmaxf(sqrtf(c), EPSN);
            out[halfOut + g] = SCALE_CLS * a / den;
        }
    }
}

extern "C" void kernel_launch(void* const* d_in, const int* in_sizes, int n_in,
                              void* d_out, int out_size)
{
    const float* ftrain = (const float*)d_in[0];
    const float* ftest  = (const float*)d_in[1];
    const int*   Kp     = (const int*)d_in[2];
    float* out = (float*)d_out;

    const int groups  = in_sizes[0] / (DD * PP);   // 1500
    const int halfOut = out_size / 2;              // 1500

    cudaFuncSetAttribute(fused_region_score_v2,
                         cudaFuncAttributeMaxDynamicSharedMemorySize, SMEM_BYTES);
    fused_region_score_v2<<<groups, NTHREADS, SMEM_BYTES>>>(ftrain, ftest, Kp,
                                                            out, halfOut);
}